// round 14
// baseline (speedup 1.0000x reference)
#include <cuda_runtime.h>
#include <cuda_fp16.h>
#include <cstdint>
#include <math.h>

// ---------------- problem constants ----------------
#define NB    16384
#define CHN   16
#define SZ    256
#define KTOT  512
#define NOUT  768

// ---------------- layout ----------------
#define NCTA     128
#define THREADS  512
#define BMROWS   128                 // segments (A rows) per CTA
#define KCHUNKS  8                   // k chunks of 64
#define NGROUPS  4                   // n-outer: 64 cols per gate each
#define NITER    (NGROUPS * KCHUNKS) // 32 B-stage iterations
#define A_SZ     (BMROWS * KTOT * 2) // 131072 bytes (A resident in smem)
#define B_STAGE  24576               // 192 rows x 128 B
#define NBSTAGE  3
#define SMEM_TOTAL (A_SZ + NBSTAGE * B_STAGE)  // 204800

// ---------------- roles ----------------
#define FCB_BLKS 16                  // CTAs 0..15: fc_b partials
#define WT_BLKS  24                  // CTAs 16..39: W transpose

// ---------------- scratch (static, no allocs) ----------------
__device__ __half g_Wt[(size_t)NOUT * KTOT];
__device__ float  g_fcb_part[CHN * SZ];
__device__ int    g_wflag;
__device__ int    g_fflag;

// ---------------- helpers ----------------
__device__ __forceinline__ uint32_t smem_u32(const void* p) {
    uint32_t a;
    asm("{ .reg .u64 t; cvta.to.shared.u64 t, %1; cvt.u32.u64 %0, t; }" : "=r"(a) : "l"(p));
    return a;
}
__device__ __forceinline__ int ld_acq(const int* p) {
    int v;
    asm volatile("ld.acquire.gpu.s32 %0, [%1];" : "=r"(v) : "l"(p) : "memory");
    return v;
}
__device__ __forceinline__ void spin_until(const int* p, int target) {
    while (ld_acq(p) < target) __nanosleep(64);
}
#define SWZ128(off) ((off) ^ (((off) >> 3) & 0x70))

#define CP_ASYNC16(sm, gp) asm volatile("cp.async.cg.shared.global [%0], [%1], 16;" :: "r"(sm), "l"(gp))
#define CP_COMMIT()        asm volatile("cp.async.commit_group;" ::: "memory")
#define CP_WAIT(n)         asm volatile("cp.async.wait_group %0;" :: "n"(n) : "memory")

#define LDMX4(r0,r1,r2,r3,addr) \
    asm volatile("ldmatrix.sync.aligned.m8n8.x4.shared.b16 {%0,%1,%2,%3}, [%4];" \
        : "=r"(r0),"=r"(r1),"=r"(r2),"=r"(r3) : "r"(addr))
#define LDMX2(r0,r1,addr) \
    asm volatile("ldmatrix.sync.aligned.m8n8.x2.shared.b16 {%0,%1}, [%2];" \
        : "=r"(r0),"=r"(r1) : "r"(addr))

#define MMA16816(c0,c1,c2,c3,a0,a1,a2,a3,b0,b1) \
    asm volatile("mma.sync.aligned.m16n8k16.row.col.f32.f16.f16.f32 " \
        "{%0,%1,%2,%3}, {%4,%5,%6,%7}, {%8,%9}, {%0,%1,%2,%3};" \
        : "+f"(c0),"+f"(c1),"+f"(c2),"+f"(c3) \
        : "r"(a0),"r"(a1),"r"(a2),"r"(a3),"r"(b0),"r"(b1))

__device__ __forceinline__ float sigf(float x) {
    return __fdividef(1.f, 1.f + __expf(-x));
}
__device__ __forceinline__ float tanh_fast(float x) {
    float e = __expf(2.f * x);
    return 1.f - __fdividef(2.f, e + 1.f);
}

// ---------------- K0: zero flags ----------------
__global__ void zero_kernel()
{
    if (threadIdx.x == 0) g_wflag = 0;
    if (threadIdx.x == 1) g_fflag = 0;
}

// ---------------- mega kernel ----------------
extern __shared__ char smem_dyn[];

// B stage loader: flat iteration it = ng*8 + kc, stage = it % 3.
// Stage holds 192 rows (3 gates x 64 cols) x 64 k fp16, SW128.
__device__ __forceinline__ void load_B(int it, uint32_t sm_base)
{
    const int tid = threadIdx.x;
    const int ng = it >> 3, kc = it & 7, st = it % NBSTAGE;
    const uint32_t base = sm_base + A_SZ + st * B_STAGE;
    #pragma unroll
    for (int i = 0; i < 3; i++) {
        int idx = tid + i * THREADS;      // 0..1535
        int r = idx >> 3, u = idx & 7;
        int g = r >> 6, j = r & 63;
        int wrow = g * 256 + ng * 64 + j;
        uint32_t so = SWZ128((uint32_t)(r * 128 + u * 16));
        CP_ASYNC16(base + so, g_Wt + (size_t)wrow * KTOT + kc * 64 + u * 8);
    }
    CP_COMMIT();
}

__global__ void __launch_bounds__(THREADS, 1)
mega_kernel(const float* __restrict__ children,
            const float* __restrict__ tracking,
            const float* __restrict__ W_iou,
            const float* __restrict__ b_iou,
            const float* __restrict__ W_f,
            const float* __restrict__ b_f,
            const float* __restrict__ W_tr,
            const float* __restrict__ W_f_track,
            float* __restrict__ out)
{
    const int bid = blockIdx.x;
    const int tid = threadIdx.x;
    const uint32_t sm_base = smem_u32(smem_dyn);

    // ===== role prologues (use A region as staging; A written later) =====
    if (bid < FCB_BLKS) {
        float* sh_ch = (float*)smem_dyn;
        float* sh_tr = sh_ch + SZ;
        const int t = bid;
        if (tid < 256) {
            const int n = tid;
            sh_ch[n] = children[(size_t)t * 512 + n];
            sh_tr[n] = tracking[n];
        }
        __syncthreads();
        if (tid < 256) {
            const int n = tid;
            float acc = b_f[n];
            #pragma unroll 8
            for (int k = 0; k < SZ; k++)
                acc += sh_ch[k] * W_f[(size_t)k * SZ + n]
                     + sh_tr[k] * W_f_track[(size_t)k * SZ + n];
            float sig = 1.f / (1.f + expf(-acc));
            g_fcb_part[t * SZ + n] = sig * children[(size_t)t * 512 + 256 + n];
        }
        __threadfence();
        __syncthreads();
        if (tid == 0) atomicAdd(&g_fflag, 1);
    } else if (bid < FCB_BLKS + WT_BLKS) {
        __half* sh = (__half*)smem_dyn;               // [32][516]
        const int n0w = (bid - FCB_BLKS) * 32;
        const int lane = tid & 31, w = tid >> 5;      // 16 warps x 32 k
        #pragma unroll 4
        for (int kk = 0; kk < 32; kk++) {
            int k = w * 32 + kk;
            float v = (k < 256) ? W_iou[(size_t)k * NOUT + n0w + lane]
                                : W_tr[(size_t)(k - 256) * NOUT + n0w + lane];
            sh[lane * 516 + k] = __float2half_rn(v);
        }
        __syncthreads();
        for (int idx = tid; idx < 32 * 128; idx += THREADS) {
            int row = idx >> 7, q = idx & 127;
            *(uint2*)&g_Wt[(size_t)(n0w + row) * KTOT + q * 4] =
                *(const uint2*)&sh[row * 516 + q * 4];
        }
        __threadfence();
        __syncthreads();
        if (tid == 0) atomicAdd(&g_wflag, 1);
    }
    __syncthreads();

    // ===== phase 1: prep all 128 segments into smem A (no globals, no flags)
    {
        const int c4 = tid & 63;              // float4 col group (k 0..255)
        const int s0 = tid >> 6;              // 0..7
        const int row0 = bid * BMROWS;
        const float4* ch = (const float4*)children;
        const float s = 1.f / (float)CHN;
        const int kg  = c4 * 4;               // mean_h k index
        const int kg2 = 256 + kg;             // tracking k index
        const uint32_t offm_c = (uint32_t)((kg >> 6) * 16384);
        const uint32_t offt_c = (uint32_t)((kg2 >> 6) * 16384);

        #pragma unroll 2
        for (int p = 0; p < 16; p++) {
            const int segl = p * 8 + s0;      // 0..127
            float4 acc = make_float4(0.f, 0.f, 0.f, 0.f);
            size_t base = (size_t)(row0 + segl) * CHN * 128 + c4;
            #pragma unroll
            for (int j = 0; j < CHN; j++) {
                float4 v = ch[base + (size_t)j * 128];
                acc.x += v.x; acc.y += v.y; acc.z += v.z; acc.w += v.w;
            }
            __half h[4];
            h[0] = __float2half_rn(acc.x * s); h[1] = __float2half_rn(acc.y * s);
            h[2] = __float2half_rn(acc.z * s); h[3] = __float2half_rn(acc.w * s);
            uint32_t off = offm_c + SWZ128((uint32_t)(segl * 128 + (kg & 63) * 2));
            *(uint2*)(smem_dyn + off) = *(uint2*)h;

            const float4 tv = ((const float4*)tracking)[(size_t)(row0 + segl) * 128 + c4];
            h[0] = __float2half_rn(tv.x); h[1] = __float2half_rn(tv.y);
            h[2] = __float2half_rn(tv.z); h[3] = __float2half_rn(tv.w);
            uint32_t off2 = offt_c + SWZ128((uint32_t)(segl * 128 + (kg2 & 63) * 2));
            *(uint2*)(smem_dyn + off2) = *(uint2*)h;
        }
    }
    __syncthreads();

    // wait for W transpose + fc_b (long done for non-first-instant CTAs)
    if (tid == 0) { spin_until(&g_wflag, WT_BLKS); spin_until(&g_fflag, FCB_BLKS); }
    __syncthreads();

    // ===== phase 2: GEMM with A in smem, B streamed from L2 =====
    const int wid  = tid >> 5;
    const int lane = tid & 31;
    const int wm   = wid >> 3;            // 0..1 -> m offset 64*wm
    const int wn   = wid & 7;             // 0..7 -> 8-col group per gate
    const int l16  = lane & 15;
    const int bgrp = lane >> 3;
    const int bg   = bgrp >> 1;           // gate 0/1
    const int bh   = bgrp & 1;            // k-half
    const int brow01 = bg * 64 + wn * 8 + (lane & 7);
    const int brow2  = 128 + wn * 8 + (lane & 7);
    const int row0 = bid * BMROWS;

    load_B(0, sm_base);
    load_B(1, sm_base);

    const int qrow = lane >> 2;

    #pragma unroll 1
    for (int ng = 0; ng < NGROUPS; ng++) {
        float acc[4][3][4];
        #pragma unroll
        for (int a = 0; a < 4; a++)
            #pragma unroll
            for (int b = 0; b < 3; b++)
                #pragma unroll
                for (int q = 0; q < 4; q++) acc[a][b][q] = 0.f;

        #pragma unroll
        for (int kc = 0; kc < KCHUNKS; kc++) {
            const int it = ng * KCHUNKS + kc;
            if (it == NITER - 1) { CP_WAIT(0); } else { CP_WAIT(1); }
            __syncthreads();

            const uint32_t stA = sm_base + kc * 16384;
            const uint32_t stB = sm_base + A_SZ + (it % NBSTAGE) * B_STAGE;

            #pragma unroll
            for (int ks = 0; ks < 4; ks++) {
                uint32_t af[4][4];
                #pragma unroll
                for (int mt = 0; mt < 4; mt++) {
                    int row = wm * 64 + mt * 16 + l16;
                    uint32_t bo = (uint32_t)(row * 128 + ks * 32 + (lane >> 4) * 16);
                    LDMX4(af[mt][0], af[mt][1], af[mt][2], af[mt][3], stA + SWZ128(bo));
                }
                uint32_t bf[3][2];
                {
                    uint32_t bo = (uint32_t)(brow01 * 128 + ks * 32 + bh * 16);
                    LDMX4(bf[0][0], bf[0][1], bf[1][0], bf[1][1], stB + SWZ128(bo));
                }
                {
                    uint32_t bo = (uint32_t)(brow2 * 128 + ks * 32 + ((lane & 15) >> 3) * 16);
                    LDMX2(bf[2][0], bf[2][1], stB + SWZ128(bo));
                }
                #pragma unroll
                for (int mt = 0; mt < 4; mt++)
                    #pragma unroll
                    for (int g = 0; g < 3; g++)
                        MMA16816(acc[mt][g][0], acc[mt][g][1], acc[mt][g][2], acc[mt][g][3],
                                 af[mt][0], af[mt][1], af[mt][2], af[mt][3],
                                 bf[g][0], bf[g][1]);
            }
            // stage (it+2)%3 == (it-1)%3: consumed before this iteration's barrier
            if (it + 2 < NITER) load_B(it + 2, sm_base);
        }

        // ---- fused epilogue for this n-group ----
        const int col0 = ng * 64 + wn * 8 + (lane & 3) * 2;
        const float bi0 = __ldg(&b_iou[col0]),       bi1 = __ldg(&b_iou[col0 + 1]);
        const float bo0 = __ldg(&b_iou[256 + col0]), bo1 = __ldg(&b_iou[256 + col0 + 1]);
        const float bu0 = __ldg(&b_iou[512 + col0]), bu1 = __ldg(&b_iou[512 + col0 + 1]);

        float f0 = 0.f, f1 = 0.f;
        #pragma unroll
        for (int tt = 0; tt < CHN; tt++) {
            float2 p = *(const float2*)&g_fcb_part[tt * SZ + col0];
            f0 += p.x; f1 += p.y;
        }

        #pragma unroll
        for (int mt = 0; mt < 4; mt++) {
            const int r0 = row0 + wm * 64 + mt * 16 + qrow;
            const int r1 = r0 + 8;

            float i00 = sigf(acc[mt][0][0] + bi0), i01 = sigf(acc[mt][0][1] + bi1);
            float i10 = sigf(acc[mt][0][2] + bi0), i11 = sigf(acc[mt][0][3] + bi1);
            float o00 = sigf(acc[mt][1][0] + bo0), o01 = sigf(acc[mt][1][1] + bo1);
            float o10 = sigf(acc[mt][1][2] + bo0), o11 = sigf(acc[mt][1][3] + bo1);
            float u00 = tanh_fast(acc[mt][2][0] + bu0), u01 = tanh_fast(acc[mt][2][1] + bu1);
            float u10 = tanh_fast(acc[mt][2][2] + bu0), u11 = tanh_fast(acc[mt][2][3] + bu1);

            float c00 = i00 * u00 + f0, c01 = i01 * u01 + f1;
            float c10 = i10 * u10 + f0, c11 = i11 * u11 + f1;

            *(float2*)&out[(size_t)r0 * 512 + col0]       = make_float2(o00 * c00, o01 * c01);
            *(float2*)&out[(size_t)r0 * 512 + 256 + col0] = make_float2(c00, c01);
            *(float2*)&out[(size_t)r1 * 512 + col0]       = make_float2(o10 * c10, o11 * c11);
            *(float2*)&out[(size_t)r1 * 512 + 256 + col0] = make_float2(c10, c11);
        }
    }
}

// ---------------- launch ----------------
extern "C" void kernel_launch(void* const* d_in, const int* in_sizes, int n_in,
                              void* d_out, int out_size)
{
    const float* children    = (const float*)d_in[0];
    const float* tracking    = (const float*)d_in[1];
    const float* W_iou       = (const float*)d_in[2];
    const float* b_iou       = (const float*)d_in[3];
    const float* W_f         = (const float*)d_in[4];
    const float* b_f         = (const float*)d_in[5];
    const float* W_iou_track = (const float*)d_in[6];
    const float* W_f_track   = (const float*)d_in[7];
    float* out = (float*)d_out;

    cudaFuncSetAttribute(mega_kernel, cudaFuncAttributeMaxDynamicSharedMemorySize, SMEM_TOTAL);

    zero_kernel<<<1, 32>>>();
    mega_kernel<<<NCTA, THREADS, SMEM_TOTAL>>>(children, tracking, W_iou, b_iou,
                                               W_f, b_f, W_iou_track, W_f_track, out);
}

// round 15
// speedup vs baseline: 1.1714x; 1.1714x over previous
#include <cuda_runtime.h>
#include <cuda_fp16.h>
#include <cstdint>
#include <math.h>

// ---------------- problem constants ----------------
#define NB    16384
#define CHN   16
#define SZ    256
#define KTOT  512
#define NOUT  768

// ---------------- GEMM tiling ----------------
#define BM 128
#define BK 64
#define NCHUNK (KTOT / BK)    // 8
#define THREADS 512
#define A_BYTES   16384       // 128 rows x 128 B
#define B_BYTES   24576       // 192 rows (3 gates x 64 cols) x 128 B
#define STAGE     (A_BYTES + B_BYTES)   // 40960
#define NSTAGE    3
#define SMEM_TOTAL (NSTAGE * STAGE)     // 122880

// ---------------- CTA roles ----------------
#define WT_BLKS   24
#define FCB_BLKS  16
#define GEMM_BASE (WT_BLKS + FCB_BLKS)   // 40
#define NTILES    512                    // (4 n-tiles) x (128 row-blocks)
#define GRID      (GEMM_BASE + NTILES)   // 552
#define NYBLK     (NB / BM)              // 128

// ---------------- scratch (static, no allocs) ----------------
__device__ __half g_Ah[(size_t)NB * KTOT];
__device__ __half g_Wt[(size_t)NOUT * KTOT];
__device__ float  g_fcb_part[CHN * SZ];
__device__ int    g_flags[NYBLK];
__device__ int    g_wflag;
__device__ int    g_fflag;

// ---------------- helpers ----------------
__device__ __forceinline__ uint32_t smem_u32(const void* p) {
    uint32_t a;
    asm("{ .reg .u64 t; cvta.to.shared.u64 t, %1; cvt.u32.u64 %0, t; }" : "=r"(a) : "l"(p));
    return a;
}
__device__ __forceinline__ int ld_acq(const int* p) {
    int v;
    asm volatile("ld.acquire.gpu.s32 %0, [%1];" : "=r"(v) : "l"(p) : "memory");
    return v;
}
__device__ __forceinline__ void spin_until(const int* p, int target) {
    while (ld_acq(p) < target) __nanosleep(64);
}
#define SWZ128(off) ((off) ^ (((off) >> 3) & 0x70))

#define CP_ASYNC16(sm, gp) asm volatile("cp.async.cg.shared.global [%0], [%1], 16;" :: "r"(sm), "l"(gp))
#define CP_COMMIT()        asm volatile("cp.async.commit_group;" ::: "memory")
#define CP_WAIT(n)         asm volatile("cp.async.wait_group %0;" :: "n"(n) : "memory")

#define LDMX4(r0,r1,r2,r3,addr) \
    asm volatile("ldmatrix.sync.aligned.m8n8.x4.shared.b16 {%0,%1,%2,%3}, [%4];" \
        : "=r"(r0),"=r"(r1),"=r"(r2),"=r"(r3) : "r"(addr))
#define LDMX2(r0,r1,addr) \
    asm volatile("ldmatrix.sync.aligned.m8n8.x2.shared.b16 {%0,%1}, [%2];" \
        : "=r"(r0),"=r"(r1) : "r"(addr))

#define MMA16816(c0,c1,c2,c3,a0,a1,a2,a3,b0,b1) \
    asm volatile("mma.sync.aligned.m16n8k16.row.col.f32.f16.f16.f32 " \
        "{%0,%1,%2,%3}, {%4,%5,%6,%7}, {%8,%9}, {%0,%1,%2,%3};" \
        : "+f"(c0),"+f"(c1),"+f"(c2),"+f"(c3) \
        : "r"(a0),"r"(a1),"r"(a2),"r"(a3),"r"(b0),"r"(b1))

__device__ __forceinline__ float sigf(float x) {
    return __fdividef(1.f, 1.f + __expf(-x));
}
__device__ __forceinline__ float tanh_fast(float x) {
    float e = __expf(2.f * x);
    return 1.f - __fdividef(2.f, e + 1.f);
}

// ---------------- K0: zero flags (fresh per launch / replay) ----------
__global__ void zero_kernel()
{
    if (threadIdx.x < NYBLK) g_flags[threadIdx.x] = 0;
    if (threadIdx.x == NYBLK)     g_wflag = 0;
    if (threadIdx.x == NYBLK + 1) g_fflag = 0;
}

// ---------------- mega kernel ----------------
extern __shared__ char smem_dyn[];

__device__ __forceinline__ void load_stage(int c, int s, uint32_t sm_base,
                                           int row0, int n0)
{
    const int tid = threadIdx.x;
    const uint32_t stA = sm_base + s * STAGE;
    const uint32_t stB = stA + A_BYTES;
    // A: 128 rows x 64 k = 1024 uint4 / 512 threads = 2 iters
    #pragma unroll
    for (int it = 0; it < 2; it++) {
        int idx = tid + it * THREADS;
        int r = idx >> 3, u = idx & 7;
        uint32_t so = SWZ128((uint32_t)(r * 128 + u * 16));
        const __half* gp = g_Ah + (size_t)(row0 + r) * KTOT + c * BK + u * 8;
        CP_ASYNC16(stA + so, gp);
    }
    // B: 192 rows x 64 k = 1536 uint4 / 512 threads = 3 iters
    #pragma unroll
    for (int it = 0; it < 3; it++) {
        int idx = tid + it * THREADS;
        int rr = idx >> 3, u = idx & 7;
        int g = rr >> 6, j = rr & 63;        // gate, col-in-64-slice
        int wrow = g * 256 + n0 + j;
        uint32_t so = SWZ128((uint32_t)(rr * 128 + u * 16));
        const __half* gp = g_Wt + (size_t)wrow * KTOT + c * BK + u * 8;
        CP_ASYNC16(stB + so, gp);
    }
    CP_COMMIT();
}

__global__ void __launch_bounds__(THREADS, 1)
mega_kernel(const float* __restrict__ children,
            const float* __restrict__ tracking,
            const float* __restrict__ W_iou,
            const float* __restrict__ b_iou,
            const float* __restrict__ W_f,
            const float* __restrict__ b_f,
            const float* __restrict__ W_tr,
            const float* __restrict__ W_f_track,
            float* __restrict__ out)
{
    const int bid = blockIdx.x;
    const int tid = threadIdx.x;

    // ================= role: W transpose =================
    if (bid < WT_BLKS) {
        __half* sh = (__half*)smem_dyn;             // [32][516]
        const int n0w = bid * 32;
        const int lane = tid & 31, w = tid >> 5;    // 16 warps x 32 k
        #pragma unroll 4
        for (int kk = 0; kk < 32; kk++) {
            int k = w * 32 + kk;
            float v = (k < 256) ? W_iou[(size_t)k * NOUT + n0w + lane]
                                : W_tr[(size_t)(k - 256) * NOUT + n0w + lane];
            sh[lane * 516 + k] = __float2half_rn(v);
        }
        __syncthreads();
        for (int idx = tid; idx < 32 * 128; idx += THREADS) {
            int row = idx >> 7, q = idx & 127;
            *(uint2*)&g_Wt[(size_t)(n0w + row) * KTOT + q * 4] =
                *(const uint2*)&sh[row * 516 + q * 4];
        }
        __threadfence();
        __syncthreads();
        if (tid == 0) atomicAdd(&g_wflag, 1);
        return;
    }

    // ================= role: fc_b partial =================
    if (bid < GEMM_BASE) {
        float* sh_ch = (float*)smem_dyn;
        float* sh_tr = sh_ch + SZ;
        const int t = bid - WT_BLKS;
        if (tid < 256) {
            sh_ch[tid] = children[(size_t)t * 512 + tid];
            sh_tr[tid] = tracking[tid];
        }
        __syncthreads();
        if (tid < 256) {
            const int n = tid;
            float acc = b_f[n];
            #pragma unroll 8
            for (int k = 0; k < SZ; k++)
                acc += sh_ch[k] * W_f[(size_t)k * SZ + n]
                     + sh_tr[k] * W_f_track[(size_t)k * SZ + n];
            float sig = 1.f / (1.f + expf(-acc));
            g_fcb_part[t * SZ + n] = sig * children[(size_t)t * 512 + 256 + n];
        }
        __threadfence();
        __syncthreads();
        if (tid == 0) atomicAdd(&g_fflag, 1);
        return;
    }

    // ================= role: GEMM tile (preps its own A slice first) ========
    const int tile = bid - GEMM_BASE;
    const int xx   = tile & 3;            // n-tile (64 cols per gate)
    const int y    = tile >> 2;           // row-block
    const int n0   = xx * 64;
    const int row0 = y * BM;

    const int wid  = tid >> 5;
    const int lane = tid & 31;
    const int wm   = wid >> 3;            // 0..1
    const int wn   = wid & 7;             // 0..7 -> 8-col group per gate

    // ---- prep: pack segments [row0 + xx*32, +32) into g_Ah ----
    {
        const int c4 = tid & 63;
        const int s0 = tid >> 6;          // 0..7
        const float4* ch = (const float4*)children;
        const float s = 1.f / (float)CHN;
        #pragma unroll
        for (int p = 0; p < 4; p++) {
            const int seg = row0 + xx * 32 + p * 8 + s0;
            float4 acc = make_float4(0.f, 0.f, 0.f, 0.f);
            size_t base = (size_t)seg * CHN * 128 + c4;
            #pragma unroll
            for (int j = 0; j < CHN; j++) {
                float4 v = ch[base + (size_t)j * 128];
                acc.x += v.x; acc.y += v.y; acc.z += v.z; acc.w += v.w;
            }
            __half h[4];
            h[0] = __float2half_rn(acc.x * s); h[1] = __float2half_rn(acc.y * s);
            h[2] = __float2half_rn(acc.z * s); h[3] = __float2half_rn(acc.w * s);
            *(uint2*)&g_Ah[(size_t)seg * KTOT + c4 * 4] = *(uint2*)h;

            const float4 tv = ((const float4*)tracking)[(size_t)seg * 128 + c4];
            h[0] = __float2half_rn(tv.x); h[1] = __float2half_rn(tv.y);
            h[2] = __float2half_rn(tv.z); h[3] = __float2half_rn(tv.w);
            *(uint2*)&g_Ah[(size_t)seg * KTOT + 256 + c4 * 4] = *(uint2*)h;
        }
    }
    __threadfence();
    __syncthreads();
    if (tid == 0) {
        atomicAdd(&g_flags[y], 1);
        spin_until(&g_wflag, WT_BLKS);
        spin_until(&g_flags[y], 4);       // 4 producer CTAs per row-block
    }
    __syncthreads();

    const uint32_t sm_base = smem_u32(smem_dyn);

    load_stage(0, 0, sm_base, row0, n0);
    load_stage(1, 1, sm_base, row0, n0);

    float acc[4][3][4];
    #pragma unroll
    for (int i = 0; i < 4; i++)
        #pragma unroll
        for (int j = 0; j < 3; j++)
            #pragma unroll
            for (int q = 0; q < 4; q++) acc[i][j][q] = 0.f;

    const int l16 = lane & 15;
    const int bgrp = lane >> 3;
    const int bg   = bgrp >> 1;
    const int bh   = bgrp & 1;
    const int brow01 = bg * 64 + wn * 8 + (lane & 7);   // gates 0,1 rows
    const int brow2  = 128 + wn * 8 + (lane & 7);       // gate 2 rows

    #pragma unroll
    for (int c = 0; c < NCHUNK; c++) {
        if (c == NCHUNK - 1) { CP_WAIT(0); } else { CP_WAIT(1); }
        __syncthreads();

        const uint32_t stA = sm_base + (c % NSTAGE) * STAGE;
        const uint32_t stB = stA + A_BYTES;

        #pragma unroll
        for (int ks = 0; ks < 4; ks++) {
            uint32_t af[4][4];
            #pragma unroll
            for (int mt = 0; mt < 4; mt++) {
                int row = wm * 64 + mt * 16 + l16;
                uint32_t bo = (uint32_t)(row * 128 + ks * 32 + (lane >> 4) * 16);
                LDMX4(af[mt][0], af[mt][1], af[mt][2], af[mt][3], stA + SWZ128(bo));
            }
            uint32_t bf[3][2];
            {
                uint32_t bo = (uint32_t)(brow01 * 128 + ks * 32 + bh * 16);
                LDMX4(bf[0][0], bf[0][1], bf[1][0], bf[1][1], stB + SWZ128(bo));
            }
            {
                uint32_t bo = (uint32_t)(brow2 * 128 + ks * 32 + ((lane & 15) >> 3) * 16);
                LDMX2(bf[2][0], bf[2][1], stB + SWZ128(bo));
            }
            #pragma unroll
            for (int mt = 0; mt < 4; mt++)
                #pragma unroll
                for (int g = 0; g < 3; g++)
                    MMA16816(acc[mt][g][0], acc[mt][g][1], acc[mt][g][2], acc[mt][g][3],
                             af[mt][0], af[mt][1], af[mt][2], af[mt][3],
                             bf[g][0], bf[g][1]);
        }
        // stage (c+2)%3 == (c-1)%3: consumed before this chunk's barrier
        if (c + 2 < NCHUNK) load_stage(c + 2, (c + 2) % NSTAGE, sm_base, row0, n0);
    }

    // ---- fused epilogue ----
    if (tid == 0) spin_until(&g_fflag, FCB_BLKS);
    __syncthreads();

    const int qrow = lane >> 2;
    const int col0 = n0 + wn * 8 + (lane & 3) * 2;
    const float bi0 = __ldg(&b_iou[col0]),       bi1 = __ldg(&b_iou[col0 + 1]);
    const float bo0 = __ldg(&b_iou[256 + col0]), bo1 = __ldg(&b_iou[256 + col0 + 1]);
    const float bu0 = __ldg(&b_iou[512 + col0]), bu1 = __ldg(&b_iou[512 + col0 + 1]);

    float f0 = 0.f, f1 = 0.f;
    #pragma unroll
    for (int t = 0; t < CHN; t++) {
        float2 p = *(const float2*)&g_fcb_part[t * SZ + col0];
        f0 += p.x; f1 += p.y;
    }

    #pragma unroll
    for (int mt = 0; mt < 4; mt++) {
        const int r0 = row0 + wm * 64 + mt * 16 + qrow;
        const int r1 = r0 + 8;

        float i00 = sigf(acc[mt][0][0] + bi0), i01 = sigf(acc[mt][0][1] + bi1);
        float i10 = sigf(acc[mt][0][2] + bi0), i11 = sigf(acc[mt][0][3] + bi1);
        float o00 = sigf(acc[mt][1][0] + bo0), o01 = sigf(acc[mt][1][1] + bo1);
        float o10 = sigf(acc[mt][1][2] + bo0), o11 = sigf(acc[mt][1][3] + bo1);
        float u00 = tanh_fast(acc[mt][2][0] + bu0), u01 = tanh_fast(acc[mt][2][1] + bu1);
        float u10 = tanh_fast(acc[mt][2][2] + bu0), u11 = tanh_fast(acc[mt][2][3] + bu1);

        float c00 = i00 * u00 + f0, c01 = i01 * u01 + f1;
        float c10 = i10 * u10 + f0, c11 = i11 * u11 + f1;

        *(float2*)&out[(size_t)r0 * 512 + col0]       = make_float2(o00 * c00, o01 * c01);
        *(float2*)&out[(size_t)r0 * 512 + 256 + col0] = make_float2(c00, c01);
        *(float2*)&out[(size_t)r1 * 512 + col0]       = make_float2(o10 * c10, o11 * c11);
        *(float2*)&out[(size_t)r1 * 512 + 256 + col0] = make_float2(c10, c11);
    }
}

// ---------------- launch ----------------
extern "C" void kernel_launch(void* const* d_in, const int* in_sizes, int n_in,
                              void* d_out, int out_size)
{
    const float* children    = (const float*)d_in[0];
    const float* tracking    = (const float*)d_in[1];
    const float* W_iou       = (const float*)d_in[2];
    const float* b_iou       = (const float*)d_in[3];
    const float* W_f         = (const float*)d_in[4];
    const float* b_f         = (const float*)d_in[5];
    const float* W_iou_track = (const float*)d_in[6];
    const float* W_f_track   = (const float*)d_in[7];
    float* out = (float*)d_out;

    cudaFuncSetAttribute(mega_kernel, cudaFuncAttributeMaxDynamicSharedMemorySize, SMEM_TOTAL);

    zero_kernel<<<1, 256>>>();
    mega_kernel<<<GRID, THREADS, SMEM_TOTAL>>>(children, tracking, W_iou, b_iou,
                                               W_f, b_f, W_iou_track, W_f_track, out);
}

// round 16
// speedup vs baseline: 1.4476x; 1.2358x over previous
#include <cuda_runtime.h>
#include <cuda_fp16.h>
#include <cstdint>
#include <math.h>

// ---------------- problem constants ----------------
#define NB    16384
#define CHN   16
#define SZ    256
#define KTOT  512
#define NOUT  768

// ---------------- GEMM tiling ----------------
#define BM 128
#define BK 64
#define NCHUNK (KTOT / BK)    // 8
#define A_BYTES   16384
#define B_BYTES   12288
#define STAGE     (A_BYTES + B_BYTES)   // 28672
#define NSTAGE    3
#define SMEM_TOTAL (NSTAGE * STAGE)     // 86016

// ---------------- CTA roles ----------------
#define WT_BLKS   24
#define FCB_BLKS  16
#define GEMM_BASE (WT_BLKS + FCB_BLKS)   // 40
#define NTILES    1024
#define GRID      (GEMM_BASE + NTILES)   // 1064
#define NYBLK     (NB / BM)              // 128

// ---------------- scratch (static, no allocs; all flags self-reset) ---------
__device__ __half g_Ah[(size_t)NB * KTOT];
__device__ __half g_Wt[(size_t)NOUT * KTOT];
__device__ float  g_fcb_part[CHN * SZ];
__device__ int    g_flags[NYBLK];        // producer arrivals per row-block
__device__ int    g_done[NYBLK];         // consumer passes per row-block
__device__ int    g_wflag, g_wdone;
__device__ int    g_fflag, g_fdone;

// ---------------- helpers ----------------
__device__ __forceinline__ uint32_t smem_u32(const void* p) {
    uint32_t a;
    asm("{ .reg .u64 t; cvta.to.shared.u64 t, %1; cvt.u32.u64 %0, t; }" : "=r"(a) : "l"(p));
    return a;
}
__device__ __forceinline__ int ld_acq(const int* p) {
    int v;
    asm volatile("ld.acquire.gpu.s32 %0, [%1];" : "=r"(v) : "l"(p) : "memory");
    return v;
}
__device__ __forceinline__ void spin_until(const int* p, int target) {
    while (ld_acq(p) < target) __nanosleep(64);
}
__device__ __forceinline__ float4 ldcs4(const float4* p) {
    float4 v;
    asm volatile("ld.global.cs.v4.f32 {%0,%1,%2,%3}, [%4];"
                 : "=f"(v.x), "=f"(v.y), "=f"(v.z), "=f"(v.w) : "l"(p));
    return v;
}
#define SWZ128(off) ((off) ^ (((off) >> 3) & 0x70))

#define CP_ASYNC16(sm, gp) asm volatile("cp.async.cg.shared.global [%0], [%1], 16;" :: "r"(sm), "l"(gp))
#define CP_COMMIT()        asm volatile("cp.async.commit_group;" ::: "memory")
#define CP_WAIT(n)         asm volatile("cp.async.wait_group %0;" :: "n"(n) : "memory")

#define LDMX4(r0,r1,r2,r3,addr) \
    asm volatile("ldmatrix.sync.aligned.m8n8.x4.shared.b16 {%0,%1,%2,%3}, [%4];" \
        : "=r"(r0),"=r"(r1),"=r"(r2),"=r"(r3) : "r"(addr))
#define LDMX2(r0,r1,addr) \
    asm volatile("ldmatrix.sync.aligned.m8n8.x2.shared.b16 {%0,%1}, [%2];" \
        : "=r"(r0),"=r"(r1) : "r"(addr))

#define MMA16816(c0,c1,c2,c3,a0,a1,a2,a3,b0,b1) \
    asm volatile("mma.sync.aligned.m16n8k16.row.col.f32.f16.f16.f32 " \
        "{%0,%1,%2,%3}, {%4,%5,%6,%7}, {%8,%9}, {%0,%1,%2,%3};" \
        : "+f"(c0),"+f"(c1),"+f"(c2),"+f"(c3) \
        : "r"(a0),"r"(a1),"r"(a2),"r"(a3),"r"(b0),"r"(b1))

__device__ __forceinline__ float sigf(float x) {
    return __fdividef(1.f, 1.f + __expf(-x));
}
__device__ __forceinline__ float tanh_fast(float x) {
    float e = __expf(2.f * x);
    return 1.f - __fdividef(2.f, e + 1.f);
}

// pass-and-maybe-reset: called by tid==0 AFTER its spin on (flag,target) passed.
// The consumer that arrives last (old == nconsumers-1) is guaranteed that all
// consumers have passed the spin; it restores both counters to 0 for the next
// launch / graph replay.
__device__ __forceinline__ void consume_reset(int* done, int* flag, int nconsumers) {
    int old = atomicAdd(done, 1);
    if (old == nconsumers - 1) {
        *flag = 0;
        *done = 0;
    }
}

// ---------------- mega kernel ----------------
extern __shared__ char smem_dyn[];

__device__ __forceinline__ void load_stage(int c, int s, uint32_t sm_base,
                                           int row0, int n0)
{
    const int tid = threadIdx.x;
    const uint32_t stA = sm_base + s * STAGE;
    const uint32_t stB = stA + A_BYTES;
    #pragma unroll
    for (int it = 0; it < 4; it++) {
        int idx = tid + it * 256;
        int r = idx >> 3, u = idx & 7;
        uint32_t so = SWZ128((uint32_t)(r * 128 + u * 16));
        const __half* gp = g_Ah + (size_t)(row0 + r) * KTOT + c * BK + u * 8;
        CP_ASYNC16(stA + so, gp);
    }
    #pragma unroll
    for (int it = 0; it < 3; it++) {
        int idx = tid + it * 256;
        int rr = idx >> 3, u = idx & 7;
        int g = rr >> 5, j = rr & 31;
        int wrow = g * 256 + n0 + j;
        uint32_t so = SWZ128((uint32_t)(rr * 128 + u * 16));
        const __half* gp = g_Wt + (size_t)wrow * KTOT + c * BK + u * 8;
        CP_ASYNC16(stB + so, gp);
    }
    CP_COMMIT();
}

__global__ __launch_bounds__(256, 2)
void mega_kernel(const float* __restrict__ children,
                 const float* __restrict__ tracking,
                 const float* __restrict__ W_iou,
                 const float* __restrict__ b_iou,
                 const float* __restrict__ W_f,
                 const float* __restrict__ b_f,
                 const float* __restrict__ W_tr,
                 const float* __restrict__ W_f_track,
                 float* __restrict__ out)
{
    const int bid = blockIdx.x;
    const int tid = threadIdx.x;

    // ================= role: W transpose =================
    if (bid < WT_BLKS) {
        __half* sh = (__half*)smem_dyn;             // [32][516]
        const int n0w = bid * 32;
        const int lane = tid & 31, w = tid >> 5;
        #pragma unroll 4
        for (int kk = 0; kk < 64; kk++) {
            int k = w * 64 + kk;
            float v = (k < 256) ? W_iou[(size_t)k * NOUT + n0w + lane]
                                : W_tr[(size_t)(k - 256) * NOUT + n0w + lane];
            sh[lane * 516 + k] = __float2half_rn(v);
        }
        __syncthreads();
        for (int idx = tid; idx < 32 * 128; idx += 256) {
            int row = idx >> 7, q = idx & 127;
            *(uint2*)&g_Wt[(size_t)(n0w + row) * KTOT + q * 4] =
                *(const uint2*)&sh[row * 516 + q * 4];
        }
        __threadfence();
        __syncthreads();
        if (tid == 0) atomicAdd(&g_wflag, 1);
        return;
    }

    // ================= role: fc_b partial =================
    if (bid < GEMM_BASE) {
        float* sh_ch = (float*)smem_dyn;
        float* sh_tr = sh_ch + SZ;
        const int t = bid - WT_BLKS;
        const int n = tid;
        sh_ch[n] = children[(size_t)t * 512 + n];
        sh_tr[n] = tracking[n];
        __syncthreads();

        float acc = b_f[n];
        #pragma unroll 8
        for (int k = 0; k < SZ; k++)
            acc += sh_ch[k] * W_f[(size_t)k * SZ + n]
                 + sh_tr[k] * W_f_track[(size_t)k * SZ + n];
        float sig = 1.f / (1.f + expf(-acc));
        g_fcb_part[t * SZ + n] = sig * children[(size_t)t * 512 + 256 + n];
        __threadfence();
        __syncthreads();
        if (tid == 0) atomicAdd(&g_fflag, 1);
        return;
    }

    // ================= role: GEMM tile (preps its own A slice first) ========
    const int tile = bid - GEMM_BASE;
    const int xx   = tile & 7;
    const int y    = tile >> 3;
    const int n0   = xx * 32;
    const int row0 = y * BM;

    const int wid  = tid >> 5;
    const int lane = tid & 31;
    const int wm   = wid >> 2;
    const int wn   = wid & 3;

    // ---- prep: pack segments [row0 + xx*16, +16) into g_Ah (streaming loads)
    {
        const int c4 = tid & 63;
        const float4* ch = (const float4*)children;
        const float s = 1.f / (float)CHN;
        #pragma unroll
        for (int p = 0; p < 4; p++) {
            const int seg = row0 + xx * 16 + p * 4 + (tid >> 6);
            float4 acc = make_float4(0.f, 0.f, 0.f, 0.f);
            size_t base = (size_t)seg * CHN * 128 + c4;
            #pragma unroll
            for (int j = 0; j < CHN; j++) {
                float4 v = ldcs4(&ch[base + (size_t)j * 128]);
                acc.x += v.x; acc.y += v.y; acc.z += v.z; acc.w += v.w;
            }
            __half h[4];
            h[0] = __float2half_rn(acc.x * s); h[1] = __float2half_rn(acc.y * s);
            h[2] = __float2half_rn(acc.z * s); h[3] = __float2half_rn(acc.w * s);
            *(uint2*)&g_Ah[(size_t)seg * KTOT + c4 * 4] = *(uint2*)h;

            const float4 tv = ldcs4(&((const float4*)tracking)[(size_t)seg * 128 + c4]);
            h[0] = __float2half_rn(tv.x); h[1] = __float2half_rn(tv.y);
            h[2] = __float2half_rn(tv.z); h[3] = __float2half_rn(tv.w);
            *(uint2*)&g_Ah[(size_t)seg * KTOT + 256 + c4 * 4] = *(uint2*)h;
        }
    }
    __threadfence();
    __syncthreads();
    if (tid == 0) {
        atomicAdd(&g_flags[y], 1);
        spin_until(&g_wflag, WT_BLKS);
        consume_reset(&g_wdone, &g_wflag, NTILES);
        spin_until(&g_flags[y], 8);
        consume_reset(&g_done[y], &g_flags[y], 8);
    }
    __syncthreads();

    const uint32_t sm_base = smem_u32(smem_dyn);

    load_stage(0, 0, sm_base, row0, n0);
    load_stage(1, 1, sm_base, row0, n0);

    float acc[4][3][4];
    #pragma unroll
    for (int i = 0; i < 4; i++)
        #pragma unroll
        for (int j = 0; j < 3; j++)
            #pragma unroll
            for (int q = 0; q < 4; q++) acc[i][j][q] = 0.f;

    const int l16 = lane & 15;
    const int bgrp = lane >> 3;
    const int bg   = bgrp >> 1;
    const int bh   = bgrp & 1;
    const int brow01 = bg * 32 + wn * 8 + (lane & 7);
    const int brow2  = 64 + wn * 8 + (lane & 7);

    #pragma unroll
    for (int c = 0; c < NCHUNK; c++) {
        if (c + 2 < NCHUNK) load_stage(c + 2, (c + 2) % NSTAGE, sm_base, row0, n0);
        if (c < NCHUNK - 2)       CP_WAIT(2);
        else if (c == NCHUNK - 2) CP_WAIT(1);
        else                      CP_WAIT(0);
        __syncthreads();

        const uint32_t stA = sm_base + (c % NSTAGE) * STAGE;
        const uint32_t stB = stA + A_BYTES;

        #pragma unroll
        for (int ks = 0; ks < 4; ks++) {
            uint32_t af[4][4];
            #pragma unroll
            for (int mt = 0; mt < 4; mt++) {
                int row = wm * 64 + mt * 16 + l16;
                uint32_t bo = (uint32_t)(row * 128 + ks * 32 + (lane >> 4) * 16);
                LDMX4(af[mt][0], af[mt][1], af[mt][2], af[mt][3], stA + SWZ128(bo));
            }
            uint32_t bf[3][2];
            {
                uint32_t bo = (uint32_t)(brow01 * 128 + ks * 32 + bh * 16);
                LDMX4(bf[0][0], bf[0][1], bf[1][0], bf[1][1], stB + SWZ128(bo));
            }
            {
                uint32_t bo = (uint32_t)(brow2 * 128 + ks * 32 + ((lane & 15) >> 3) * 16);
                LDMX2(bf[2][0], bf[2][1], stB + SWZ128(bo));
            }
            #pragma unroll
            for (int mt = 0; mt < 4; mt++)
                #pragma unroll
                for (int g = 0; g < 3; g++)
                    MMA16816(acc[mt][g][0], acc[mt][g][1], acc[mt][g][2], acc[mt][g][3],
                             af[mt][0], af[mt][1], af[mt][2], af[mt][3],
                             bf[g][0], bf[g][1]);
        }
        __syncthreads();
    }

    // ---- fused epilogue ----
    if (tid == 0) {
        spin_until(&g_fflag, FCB_BLKS);
        consume_reset(&g_fdone, &g_fflag, NTILES);
    }
    __syncthreads();

    const int qrow = lane >> 2;
    const int col0 = n0 + wn * 8 + (lane & 3) * 2;
    const float bi0 = __ldg(&b_iou[col0]),       bi1 = __ldg(&b_iou[col0 + 1]);
    const float bo0 = __ldg(&b_iou[256 + col0]), bo1 = __ldg(&b_iou[256 + col0 + 1]);
    const float bu0 = __ldg(&b_iou[512 + col0]), bu1 = __ldg(&b_iou[512 + col0 + 1]);

    float f0 = 0.f, f1 = 0.f;
    #pragma unroll
    for (int t = 0; t < CHN; t++) {
        float2 p = *(const float2*)&g_fcb_part[t * SZ + col0];
        f0 += p.x; f1 += p.y;
    }

    #pragma unroll
    for (int mt = 0; mt < 4; mt++) {
        const int r0 = row0 + wm * 64 + mt * 16 + qrow;
        const int r1 = r0 + 8;

        float i00 = sigf(acc[mt][0][0] + bi0), i01 = sigf(acc[mt][0][1] + bi1);
        float i10 = sigf(acc[mt][0][2] + bi0), i11 = sigf(acc[mt][0][3] + bi1);
        float o00 = sigf(acc[mt][1][0] + bo0), o01 = sigf(acc[mt][1][1] + bo1);
        float o10 = sigf(acc[mt][1][2] + bo0), o11 = sigf(acc[mt][1][3] + bo1);
        float u00 = tanh_fast(acc[mt][2][0] + bu0), u01 = tanh_fast(acc[mt][2][1] + bu1);
        float u10 = tanh_fast(acc[mt][2][2] + bu0), u11 = tanh_fast(acc[mt][2][3] + bu1);

        float c00 = i00 * u00 + f0, c01 = i01 * u01 + f1;
        float c10 = i10 * u10 + f0, c11 = i11 * u11 + f1;

        *(float2*)&out[(size_t)r0 * 512 + col0]       = make_float2(o00 * c00, o01 * c01);
        *(float2*)&out[(size_t)r0 * 512 + 256 + col0] = make_float2(c00, c01);
        *(float2*)&out[(size_t)r1 * 512 + col0]       = make_float2(o10 * c10, o11 * c11);
        *(float2*)&out[(size_t)r1 * 512 + 256 + col0] = make_float2(c10, c11);
    }
}

// ---------------- launch ----------------
extern "C" void kernel_launch(void* const* d_in, const int* in_sizes, int n_in,
                              void* d_out, int out_size)
{
    const float* children    = (const float*)d_in[0];
    const float* tracking    = (const float*)d_in[1];
    const float* W_iou       = (const float*)d_in[2];
    const float* b_iou       = (const float*)d_in[3];
    const float* W_f         = (const float*)d_in[4];
    const float* b_f         = (const float*)d_in[5];
    const float* W_iou_track = (const float*)d_in[6];
    const float* W_f_track   = (const float*)d_in[7];
    float* out = (float*)d_out;

    cudaFuncSetAttribute(mega_kernel, cudaFuncAttributeMaxDynamicSharedMemorySize, SMEM_TOTAL);

    mega_kernel<<<GRID, 256, SMEM_TOTAL>>>(children, tracking, W_iou, b_iou,
                                           W_f, b_f, W_iou_track, W_f_track, out);
}